// round 5
// baseline (speedup 1.0000x reference)
#include <cuda_runtime.h>
#include <cuda_bf16.h>
#include <math.h>

#define MAX_N 50000
#define MAX_E 800000
#define CH    96
#define BN_EPS 1e-5f

// -------- scratch (device globals; no allocation allowed) --------
__device__ float d_t   [MAX_N * CH];     // GEMM output (pre-aggregation)
__device__ float d_agg [MAX_N * CH];     // aggregation output
__device__ float d_stats[2 * CH];        // per-channel sum / sumsq
__device__ float d_scale[CH];
__device__ float d_shift[CH];
// CSR build scratch
__device__ int   d_deg   [MAX_N];
__device__ int   d_starts[MAX_N + 1];
__device__ int   d_cursor[MAX_N];
__device__ int2  d_epack [MAX_E];        // packed (col, bitcast(ew))

// ============================================================================
// CSR build: histogram -> scan -> permute
// ============================================================================
__global__ void hist_kernel(const int* __restrict__ row, int* __restrict__ deg, int E) {
    int i = blockIdx.x * blockDim.x + threadIdx.x;
    if (i < E) atomicAdd(&deg[row[i]], 1);
}

__global__ void scan_kernel(const int* __restrict__ deg,
                            int* __restrict__ starts,
                            int* __restrict__ cursor, int N) {
    __shared__ int part[1024];
    int t = threadIdx.x;
    int chunk = (N + 1023) / 1024;
    int lo = t * chunk;
    int hi = lo + chunk; if (hi > N) hi = N; if (lo > N) lo = N;
    int s = 0;
    for (int i = lo; i < hi; i++) s += deg[i];
    part[t] = s;
    __syncthreads();
    for (int o = 1; o < 1024; o <<= 1) {
        int v = (t >= o) ? part[t - o] : 0;
        __syncthreads();
        part[t] += v;
        __syncthreads();
    }
    int base = (t == 0) ? 0 : part[t - 1];
    for (int i = lo; i < hi; i++) {
        starts[i] = base;
        cursor[i] = base;
        base += deg[i];
    }
    if (t == 1023) starts[N] = part[1023];
}

__global__ void permute_kernel(const int* __restrict__ row,
                               const int* __restrict__ col,
                               const float* __restrict__ ew,
                               int* __restrict__ cursor,
                               int2* __restrict__ epack, int E) {
    int i = blockIdx.x * blockDim.x + threadIdx.x;
    if (i >= E) return;
    int p = atomicAdd(&cursor[row[i]], 1);
    epack[p] = make_int2(col[i], __float_as_int(ew[i]));
}

// ============================================================================
// Register-blocked GEMM, K-chunked (KC=32), thread tile 8 rows x 4 cols.
// TM=64 rows per block; optional fused BatchNorm+ReLU on the INPUT.
// ============================================================================
template<int CIN, int COUT>
__global__ void gemm_bn_kernel(const float* __restrict__ A,
                               const float* __restrict__ W,
                               const float* __restrict__ scale,
                               const float* __restrict__ shift,
                               float* __restrict__ C, int nrows) {
    constexpr int TM = 64;
    constexpr int KC = 32;
    constexpr int TX = COUT / 4;      // thread cols (4 outputs each)
    constexpr int TY = 8;             // thread rows (8 outputs each)
    constexpr int NT = TX * TY;
    constexpr int APAD = TM + 4;      // 68
    constexpr int KGC = KC / 4;

    __shared__ float Ws[KC * COUT];
    __shared__ float As[KC * APAD];

    int tid = threadIdx.y * TX + threadIdx.x;
    int row0 = blockIdx.x * TM;
    int c0 = threadIdx.x * 4;
    int r0 = threadIdx.y * 8;

    float4 acc[8];
#pragma unroll
    for (int r = 0; r < 8; r++) acc[r] = make_float4(0.f, 0.f, 0.f, 0.f);

    for (int k0 = 0; k0 < CIN; k0 += KC) {
        // stage W chunk (coalesced float4)
        for (int i = tid; i < KC * COUT / 4; i += NT)
            ((float4*)Ws)[i] = ((const float4*)(W + k0 * COUT))[i];
        // stage A chunk transposed, optional BN+ReLU
        for (int i = tid; i < TM * KGC; i += NT) {
            int r  = i / KGC;
            int kg = i % KGC;
            int grow = row0 + r;
            float4 v = make_float4(0.f, 0.f, 0.f, 0.f);
            if (grow < nrows)
                v = *(const float4*)(A + (long)grow * CIN + k0 + kg * 4);
            if (scale) {
                int k = k0 + kg * 4;
                v.x = fmaxf(fmaf(v.x, scale[k+0], shift[k+0]), 0.f);
                v.y = fmaxf(fmaf(v.y, scale[k+1], shift[k+1]), 0.f);
                v.z = fmaxf(fmaf(v.z, scale[k+2], shift[k+2]), 0.f);
                v.w = fmaxf(fmaf(v.w, scale[k+3], shift[k+3]), 0.f);
            }
            As[(kg*4+0) * APAD + r] = v.x;
            As[(kg*4+1) * APAD + r] = v.y;
            As[(kg*4+2) * APAD + r] = v.z;
            As[(kg*4+3) * APAD + r] = v.w;
        }
        __syncthreads();

#pragma unroll 4
        for (int kk = 0; kk < KC; kk++) {
            float4 w  = *(const float4*)(Ws + kk * COUT + c0);
            float4 a0 = *(const float4*)(As + kk * APAD + r0);
            float4 a1 = *(const float4*)(As + kk * APAD + r0 + 4);
            acc[0].x = fmaf(a0.x, w.x, acc[0].x); acc[0].y = fmaf(a0.x, w.y, acc[0].y);
            acc[0].z = fmaf(a0.x, w.z, acc[0].z); acc[0].w = fmaf(a0.x, w.w, acc[0].w);
            acc[1].x = fmaf(a0.y, w.x, acc[1].x); acc[1].y = fmaf(a0.y, w.y, acc[1].y);
            acc[1].z = fmaf(a0.y, w.z, acc[1].z); acc[1].w = fmaf(a0.y, w.w, acc[1].w);
            acc[2].x = fmaf(a0.z, w.x, acc[2].x); acc[2].y = fmaf(a0.z, w.y, acc[2].y);
            acc[2].z = fmaf(a0.z, w.z, acc[2].z); acc[2].w = fmaf(a0.z, w.w, acc[2].w);
            acc[3].x = fmaf(a0.w, w.x, acc[3].x); acc[3].y = fmaf(a0.w, w.y, acc[3].y);
            acc[3].z = fmaf(a0.w, w.z, acc[3].z); acc[3].w = fmaf(a0.w, w.w, acc[3].w);
            acc[4].x = fmaf(a1.x, w.x, acc[4].x); acc[4].y = fmaf(a1.x, w.y, acc[4].y);
            acc[4].z = fmaf(a1.x, w.z, acc[4].z); acc[4].w = fmaf(a1.x, w.w, acc[4].w);
            acc[5].x = fmaf(a1.y, w.x, acc[5].x); acc[5].y = fmaf(a1.y, w.y, acc[5].y);
            acc[5].z = fmaf(a1.y, w.z, acc[5].z); acc[5].w = fmaf(a1.y, w.w, acc[5].w);
            acc[6].x = fmaf(a1.z, w.x, acc[6].x); acc[6].y = fmaf(a1.z, w.y, acc[6].y);
            acc[6].z = fmaf(a1.z, w.z, acc[6].z); acc[6].w = fmaf(a1.z, w.w, acc[6].w);
            acc[7].x = fmaf(a1.w, w.x, acc[7].x); acc[7].y = fmaf(a1.w, w.y, acc[7].y);
            acc[7].z = fmaf(a1.w, w.z, acc[7].z); acc[7].w = fmaf(a1.w, w.w, acc[7].w);
        }
        __syncthreads();
    }

#pragma unroll
    for (int r = 0; r < 8; r++) {
        int grow = row0 + r0 + r;
        if (grow < nrows)
            *(float4*)(C + (long)grow * COUT + c0) = acc[r];
    }
}

// ============================================================================
// CSR gather (96 ch, no atomics): one warp per node, lanes 0-23 each own a
// float4 channel group. Unrolled by 4 edges -> 4 independent LDG.128 in flight.
// ============================================================================
__global__ void gather96_kernel(const int* __restrict__ starts,
                                const int2* __restrict__ epack,
                                const float* __restrict__ src,
                                float* __restrict__ dst, int N) {
    int w = (blockIdx.x * blockDim.x + threadIdx.x) >> 5;
    int lane = threadIdx.x & 31;
    if (w >= N) return;
    int s = __ldg(starts + w), e = __ldg(starts + w + 1);
    bool act = lane < 24;
    float4 acc0 = make_float4(0.f,0.f,0.f,0.f);
    float4 acc1 = make_float4(0.f,0.f,0.f,0.f);
    int i = s;
    for (; i + 3 < e; i += 4) {
        int2 p0 = __ldg(epack + i);
        int2 p1 = __ldg(epack + i + 1);
        int2 p2 = __ldg(epack + i + 2);
        int2 p3 = __ldg(epack + i + 3);
        float4 v0 = make_float4(0,0,0,0), v1 = v0, v2 = v0, v3 = v0;
        if (act) {
            v0 = __ldg(((const float4*)(src + (long)p0.x * 96)) + lane);
            v1 = __ldg(((const float4*)(src + (long)p1.x * 96)) + lane);
            v2 = __ldg(((const float4*)(src + (long)p2.x * 96)) + lane);
            v3 = __ldg(((const float4*)(src + (long)p3.x * 96)) + lane);
        }
        float w0 = __int_as_float(p0.y), w1 = __int_as_float(p1.y);
        float w2 = __int_as_float(p2.y), w3 = __int_as_float(p3.y);
        acc0.x = fmaf(w0, v0.x, acc0.x); acc0.y = fmaf(w0, v0.y, acc0.y);
        acc0.z = fmaf(w0, v0.z, acc0.z); acc0.w = fmaf(w0, v0.w, acc0.w);
        acc1.x = fmaf(w1, v1.x, acc1.x); acc1.y = fmaf(w1, v1.y, acc1.y);
        acc1.z = fmaf(w1, v1.z, acc1.z); acc1.w = fmaf(w1, v1.w, acc1.w);
        acc0.x = fmaf(w2, v2.x, acc0.x); acc0.y = fmaf(w2, v2.y, acc0.y);
        acc0.z = fmaf(w2, v2.z, acc0.z); acc0.w = fmaf(w2, v2.w, acc0.w);
        acc1.x = fmaf(w3, v3.x, acc1.x); acc1.y = fmaf(w3, v3.y, acc1.y);
        acc1.z = fmaf(w3, v3.z, acc1.z); acc1.w = fmaf(w3, v3.w, acc1.w);
    }
    for (; i < e; i++) {
        int2 p = __ldg(epack + i);
        float4 v = make_float4(0,0,0,0);
        if (act) v = __ldg(((const float4*)(src + (long)p.x * 96)) + lane);
        float cw = __int_as_float(p.y);
        acc0.x = fmaf(cw, v.x, acc0.x); acc0.y = fmaf(cw, v.y, acc0.y);
        acc0.z = fmaf(cw, v.z, acc0.z); acc0.w = fmaf(cw, v.w, acc0.w);
    }
    acc0.x += acc1.x; acc0.y += acc1.y; acc0.z += acc1.z; acc0.w += acc1.w;
    if (act) ((float4*)(dst + (long)w * 96))[lane] = acc0;
}

// ============================================================================
// CSR gather (64 ch): half-warps own alternating edges, unroll-2 per half
// (4 edges in flight). Fused +bias + log_softmax.
// ============================================================================
__global__ void gather64_lsm_kernel(const int* __restrict__ starts,
                                    const int2* __restrict__ epack,
                                    const float* __restrict__ src,
                                    const float* __restrict__ b,
                                    float* __restrict__ out, int N) {
    int w = (blockIdx.x * blockDim.x + threadIdx.x) >> 5;
    int lane = threadIdx.x & 31;
    if (w >= N) return;
    int half = lane >> 4;
    int q = lane & 15;
    int s = __ldg(starts + w), e = __ldg(starts + w + 1);
    float4 acc0 = make_float4(0.f,0.f,0.f,0.f);
    float4 acc1 = make_float4(0.f,0.f,0.f,0.f);
    int i = s + half;
    for (; i + 2 < e; i += 4) {
        int2 p0 = __ldg(epack + i);
        int2 p1 = __ldg(epack + i + 2);
        float4 v0 = __ldg(((const float4*)(src + (long)p0.x * 64)) + q);
        float4 v1 = __ldg(((const float4*)(src + (long)p1.x * 64)) + q);
        float w0 = __int_as_float(p0.y), w1 = __int_as_float(p1.y);
        acc0.x = fmaf(w0, v0.x, acc0.x); acc0.y = fmaf(w0, v0.y, acc0.y);
        acc0.z = fmaf(w0, v0.z, acc0.z); acc0.w = fmaf(w0, v0.w, acc0.w);
        acc1.x = fmaf(w1, v1.x, acc1.x); acc1.y = fmaf(w1, v1.y, acc1.y);
        acc1.z = fmaf(w1, v1.z, acc1.z); acc1.w = fmaf(w1, v1.w, acc1.w);
    }
    for (; i < e; i += 2) {
        int2 p = __ldg(epack + i);
        float4 v = __ldg(((const float4*)(src + (long)p.x * 64)) + q);
        float cw = __int_as_float(p.y);
        acc0.x = fmaf(cw, v.x, acc0.x); acc0.y = fmaf(cw, v.y, acc0.y);
        acc0.z = fmaf(cw, v.z, acc0.z); acc0.w = fmaf(cw, v.w, acc0.w);
    }
    acc0.x += acc1.x; acc0.y += acc1.y; acc0.z += acc1.z; acc0.w += acc1.w;
    acc0.x += __shfl_xor_sync(0xFFFFFFFFu, acc0.x, 16);
    acc0.y += __shfl_xor_sync(0xFFFFFFFFu, acc0.y, 16);
    acc0.z += __shfl_xor_sync(0xFFFFFFFFu, acc0.z, 16);
    acc0.w += __shfl_xor_sync(0xFFFFFFFFu, acc0.w, 16);
    float4 bb = __ldg(((const float4*)b) + q);
    float v0 = acc0.x + bb.x, v1 = acc0.y + bb.y, v2 = acc0.z + bb.z, v3 = acc0.w + bb.w;
    float m = fmaxf(fmaxf(v0, v1), fmaxf(v2, v3));
#pragma unroll
    for (int o = 8; o; o >>= 1) m = fmaxf(m, __shfl_xor_sync(0xFFFFFFFFu, m, o));
    float sm = __expf(v0 - m) + __expf(v1 - m) + __expf(v2 - m) + __expf(v3 - m);
#pragma unroll
    for (int o = 8; o; o >>= 1) sm += __shfl_xor_sync(0xFFFFFFFFu, sm, o);
    float l = m + __logf(sm);
    if (half == 0)
        ((float4*)(out + (long)w * 64))[q] = make_float4(v0 - l, v1 - l, v2 - l, v3 - l);
}

// -------- BN stats: register-accumulating, one thread per channel ----------
__global__ void stats96_kernel(const float* __restrict__ h,
                               float* __restrict__ stats, int nrows) {
    int c = threadIdx.x;   // blockDim.x == 96
    float s = 0.f, q = 0.f;
    for (int r = blockIdx.x; r < nrows; r += gridDim.x) {
        float v = h[(long)r * 96 + c];
        s += v;
        q = fmaf(v, v, q);
    }
    atomicAdd(&stats[c], s);
    atomicAdd(&stats[96 + c], q);
}

// -------- BN finalize: per-channel scale/shift --------
__global__ void bn_finalize_kernel(const float* __restrict__ stats,
                                   const float* __restrict__ gamma,
                                   const float* __restrict__ beta,
                                   float* __restrict__ scale,
                                   float* __restrict__ shift, int nrows) {
    int c = threadIdx.x;
    if (c >= 96) return;
    float n = (float)nrows;
    float mean = stats[c] / n;
    float var = stats[96 + c] / n - mean * mean;
    float inv = rsqrtf(var + BN_EPS);
    float sc = gamma[c] * inv;
    scale[c] = sc;
    shift[c] = beta[c] - mean * sc;
}

// ============================================================================
extern "C" void kernel_launch(void* const* d_in, const int* in_sizes, int n_in,
                              void* d_out, int out_size) {
    const float* x   = (const float*)d_in[0];
    const float* ew  = (const float*)d_in[1];
    const int*   row = (const int*)  d_in[2];
    const int*   col = (const int*)  d_in[3];
    const float* W1  = (const float*)d_in[4];
    // b1 = d_in[5]  -- absorbed exactly by BatchNorm mean, skipped
    const float* W2  = (const float*)d_in[6];
    // b2 = d_in[7]  -- absorbed exactly by BatchNorm mean, skipped
    const float* W3  = (const float*)d_in[8];
    const float* b3  = (const float*)d_in[9];
    const float* g1  = (const float*)d_in[10];
    const float* be1 = (const float*)d_in[11];
    const float* g2  = (const float*)d_in[12];
    const float* be2 = (const float*)d_in[13];

    int N = in_sizes[0] / 128;
    int E = in_sizes[1];
    if (N > MAX_N) N = MAX_N;
    if (E > MAX_E) E = MAX_E;
    float* out = (float*)d_out;

    float *t, *agg, *stats, *scale, *shift;
    int *deg, *starts, *cursor;
    int2 *epack;
    cudaGetSymbolAddress((void**)&t,      d_t);
    cudaGetSymbolAddress((void**)&agg,    d_agg);
    cudaGetSymbolAddress((void**)&stats,  d_stats);
    cudaGetSymbolAddress((void**)&scale,  d_scale);
    cudaGetSymbolAddress((void**)&shift,  d_shift);
    cudaGetSymbolAddress((void**)&deg,    d_deg);
    cudaGetSymbolAddress((void**)&starts, d_starts);
    cudaGetSymbolAddress((void**)&cursor, d_cursor);
    cudaGetSymbolAddress((void**)&epack,  d_epack);

    int gblocks = (N + 63) / 64;
    int eblocks = (E + 255) / 256;
    int nwarp_blocks = (N * 32 + 255) / 256;

    // ---------------- CSR build (row-sorted packed edges) ----------------
    cudaMemsetAsync(deg, 0, (long)N * sizeof(int));
    hist_kernel<<<eblocks, 256>>>(row, deg, E);
    scan_kernel<<<1, 1024>>>(deg, starts, cursor, N);
    permute_kernel<<<eblocks, 256>>>(row, col, ew, cursor, epack, E);

    // ---------------- Layer 1: x[N,128] @ W1 -> gather -> agg ----------------
    cudaMemsetAsync(stats, 0, 192 * sizeof(float));
    gemm_bn_kernel<128,96><<<gblocks, dim3(24,8)>>>(x, W1, nullptr, nullptr, t, N);
    gather96_kernel<<<nwarp_blocks, 256>>>(starts, epack, t, agg, N);
    stats96_kernel<<<1024, 96>>>(agg, stats, N);
    bn_finalize_kernel<<<1, 96>>>(stats, g1, be1, scale, shift, N);

    // ---------------- Layer 2: relu(bn(agg)) @ W2 -> gather -> agg -----------
    gemm_bn_kernel<96,96><<<gblocks, dim3(24,8)>>>(agg, W2, scale, shift, t, N);
    cudaMemsetAsync(stats, 0, 192 * sizeof(float));
    gather96_kernel<<<nwarp_blocks, 256>>>(starts, epack, t, agg, N);
    stats96_kernel<<<1024, 96>>>(agg, stats, N);
    bn_finalize_kernel<<<1, 96>>>(stats, g2, be2, scale, shift, N);

    // ---------------- Layer 3: relu(bn(agg)) @ W3 -> gather+lsm -> out -------
    gemm_bn_kernel<96,64><<<gblocks, dim3(16,8)>>>(agg, W3, scale, shift, t, N);
    gather64_lsm_kernel<<<nwarp_blocks, 256>>>(starts, epack, t, b3, out, N);
}

// round 6
// speedup vs baseline: 1.0241x; 1.0241x over previous
#include <cuda_runtime.h>
#include <cuda_bf16.h>
#include <math.h>

#define MAX_N 50000
#define MAX_E 800000
#define CH    96
#define BN_EPS 1e-5f

// -------- scratch (device globals; no allocation allowed) --------
__device__ float d_t   [MAX_N * CH];     // GEMM output (pre-aggregation)
__device__ float d_agg [MAX_N * CH];     // aggregation output
__device__ float d_stats[4 * CH];        // [sum1|sq1|sum2|sq2] (192 floats x2)
// CSR build scratch
__device__ int   d_deg   [MAX_N];
__device__ int   d_starts[MAX_N + 1];
__device__ int   d_cursor[MAX_N];
__device__ int2  d_epack [MAX_E];        // packed (col, bitcast(ew))

// ============================================================================
// CSR build: histogram -> scan (also zeros stats) -> permute
// ============================================================================
__global__ void hist_kernel(const int* __restrict__ row, int* __restrict__ deg, int E) {
    int i = blockIdx.x * blockDim.x + threadIdx.x;
    if (i < E) atomicAdd(&deg[row[i]], 1);
}

__global__ void scan_kernel(const int* __restrict__ deg,
                            int* __restrict__ starts,
                            int* __restrict__ cursor,
                            float* __restrict__ stats, int N) {
    __shared__ int part[1024];
    int t = threadIdx.x;
    if (t < 4 * CH) stats[t] = 0.f;
    int chunk = (N + 1023) / 1024;
    int lo = t * chunk;
    int hi = lo + chunk; if (hi > N) hi = N; if (lo > N) lo = N;
    int s = 0;
    for (int i = lo; i < hi; i++) s += deg[i];
    part[t] = s;
    __syncthreads();
    for (int o = 1; o < 1024; o <<= 1) {
        int v = (t >= o) ? part[t - o] : 0;
        __syncthreads();
        part[t] += v;
        __syncthreads();
    }
    int base = (t == 0) ? 0 : part[t - 1];
    for (int i = lo; i < hi; i++) {
        starts[i] = base;
        cursor[i] = base;
        base += deg[i];
    }
    if (t == 1023) starts[N] = part[1023];
}

__global__ void permute_kernel(const int* __restrict__ row,
                               const int* __restrict__ col,
                               const float* __restrict__ ew,
                               int* __restrict__ cursor,
                               int2* __restrict__ epack, int E) {
    int i = blockIdx.x * blockDim.x + threadIdx.x;
    if (i >= E) return;
    int p = atomicAdd(&cursor[row[i]], 1);
    epack[p] = make_int2(col[i], __float_as_int(ew[i]));
}

// ============================================================================
// Register-blocked GEMM, K-chunked (KC=32), 32 rows/block, 4x4 per thread.
// Optional fused BatchNorm+ReLU on the INPUT: scale/shift computed per block
// from raw stats (sum/sumsq) + gamma/beta in a tiny prologue.
// ============================================================================
template<int CIN, int COUT>
__global__ void gemm_bn_kernel(const float* __restrict__ A,
                               const float* __restrict__ W,
                               const float* __restrict__ stats,
                               const float* __restrict__ gamma,
                               const float* __restrict__ beta,
                               float* __restrict__ C, int nrows) {
    constexpr int TM = 32;
    constexpr int KC = 32;
    constexpr int TX = COUT / 4;
    constexpr int TY = TM / 4;
    constexpr int NT = TX * TY;
    constexpr int APAD = TM + 4;
    constexpr int KGC = KC / 4;

    __shared__ float Ws[KC * COUT];
    __shared__ float As[KC * APAD];
    __shared__ float Sc[CIN];
    __shared__ float Sh[CIN];

    int tid = threadIdx.y * TX + threadIdx.x;
    int row0 = blockIdx.x * TM;
    int c0 = threadIdx.x * 4;
    int r0 = threadIdx.y * 4;

    bool has_bn = (gamma != nullptr);
    if (has_bn) {
        float n = (float)nrows;
        for (int i = tid; i < CIN; i += NT) {
            float mean = stats[i] / n;
            float var  = stats[CIN + i] / n - mean * mean;
            float inv  = rsqrtf(var + BN_EPS);
            float sc   = gamma[i] * inv;
            Sc[i] = sc;
            Sh[i] = beta[i] - mean * sc;
        }
        __syncthreads();
    }

    float acc00=0,acc01=0,acc02=0,acc03=0;
    float acc10=0,acc11=0,acc12=0,acc13=0;
    float acc20=0,acc21=0,acc22=0,acc23=0;
    float acc30=0,acc31=0,acc32=0,acc33=0;

    for (int k0 = 0; k0 < CIN; k0 += KC) {
        for (int i = tid; i < KC * COUT / 4; i += NT)
            ((float4*)Ws)[i] = ((const float4*)(W + k0 * COUT))[i];
        for (int i = tid; i < TM * KGC; i += NT) {
            int r  = i / KGC;
            int kg = i % KGC;
            int grow = row0 + r;
            float4 v = make_float4(0.f, 0.f, 0.f, 0.f);
            if (grow < nrows)
                v = *(const float4*)(A + (long)grow * CIN + k0 + kg * 4);
            if (has_bn) {
                int k = k0 + kg * 4;
                v.x = fmaxf(fmaf(v.x, Sc[k+0], Sh[k+0]), 0.f);
                v.y = fmaxf(fmaf(v.y, Sc[k+1], Sh[k+1]), 0.f);
                v.z = fmaxf(fmaf(v.z, Sc[k+2], Sh[k+2]), 0.f);
                v.w = fmaxf(fmaf(v.w, Sc[k+3], Sh[k+3]), 0.f);
            }
            As[(kg*4+0) * APAD + r] = v.x;
            As[(kg*4+1) * APAD + r] = v.y;
            As[(kg*4+2) * APAD + r] = v.z;
            As[(kg*4+3) * APAD + r] = v.w;
        }
        __syncthreads();

#pragma unroll 8
        for (int kk = 0; kk < KC; kk++) {
            float4 w = *(const float4*)(Ws + kk * COUT + c0);
            const float* ar = As + kk * APAD + r0;
            float a0 = ar[0], a1 = ar[1], a2 = ar[2], a3 = ar[3];
            acc00 = fmaf(a0, w.x, acc00); acc01 = fmaf(a0, w.y, acc01);
            acc02 = fmaf(a0, w.z, acc02); acc03 = fmaf(a0, w.w, acc03);
            acc10 = fmaf(a1, w.x, acc10); acc11 = fmaf(a1, w.y, acc11);
            acc12 = fmaf(a1, w.z, acc12); acc13 = fmaf(a1, w.w, acc13);
            acc20 = fmaf(a2, w.x, acc20); acc21 = fmaf(a2, w.y, acc21);
            acc22 = fmaf(a2, w.z, acc22); acc23 = fmaf(a2, w.w, acc23);
            acc30 = fmaf(a3, w.x, acc30); acc31 = fmaf(a3, w.y, acc31);
            acc32 = fmaf(a3, w.z, acc32); acc33 = fmaf(a3, w.w, acc33);
        }
        __syncthreads();
    }

    long base = (long)(row0 + r0) * COUT + c0;
    if (row0 + r0 + 0 < nrows) *(float4*)(C + base + 0L*COUT) = make_float4(acc00,acc01,acc02,acc03);
    if (row0 + r0 + 1 < nrows) *(float4*)(C + base + 1L*COUT) = make_float4(acc10,acc11,acc12,acc13);
    if (row0 + r0 + 2 < nrows) *(float4*)(C + base + 2L*COUT) = make_float4(acc20,acc21,acc22,acc23);
    if (row0 + r0 + 3 < nrows) *(float4*)(C + base + 3L*COUT) = make_float4(acc30,acc31,acc32,acc33);
}

// ============================================================================
// CSR gather (96 ch) with FUSED BN-stats accumulation (smem -> one atomic
// flush per block). One warp per node; lanes 0-23 own float4 channel groups.
// Unrolled by 4 edges for MLP.
// ============================================================================
__global__ void gather96_stats_kernel(const int* __restrict__ starts,
                                      const int2* __restrict__ epack,
                                      const float* __restrict__ src,
                                      float* __restrict__ dst,
                                      float* __restrict__ stats, int N) {
    __shared__ float ss[2 * CH];   // sum[96], sumsq[96]
    int tid = threadIdx.x;
    if (tid < 2 * CH) ss[tid] = 0.f;
    __syncthreads();

    int w = (blockIdx.x * blockDim.x + tid) >> 5;
    int lane = tid & 31;
    bool valid = w < N;
    bool act = valid && (lane < 24);

    int s = 0, e = 0;
    if (valid) { s = __ldg(starts + w); e = __ldg(starts + w + 1); }

    float4 acc0 = make_float4(0.f,0.f,0.f,0.f);
    float4 acc1 = make_float4(0.f,0.f,0.f,0.f);
    int i = s;
    for (; i + 3 < e; i += 4) {
        int2 p0 = __ldg(epack + i);
        int2 p1 = __ldg(epack + i + 1);
        int2 p2 = __ldg(epack + i + 2);
        int2 p3 = __ldg(epack + i + 3);
        float4 v0 = make_float4(0,0,0,0), v1 = v0, v2 = v0, v3 = v0;
        if (act) {
            v0 = __ldg(((const float4*)(src + (long)p0.x * 96)) + lane);
            v1 = __ldg(((const float4*)(src + (long)p1.x * 96)) + lane);
            v2 = __ldg(((const float4*)(src + (long)p2.x * 96)) + lane);
            v3 = __ldg(((const float4*)(src + (long)p3.x * 96)) + lane);
        }
        float w0 = __int_as_float(p0.y), w1 = __int_as_float(p1.y);
        float w2 = __int_as_float(p2.y), w3 = __int_as_float(p3.y);
        acc0.x = fmaf(w0, v0.x, acc0.x); acc0.y = fmaf(w0, v0.y, acc0.y);
        acc0.z = fmaf(w0, v0.z, acc0.z); acc0.w = fmaf(w0, v0.w, acc0.w);
        acc1.x = fmaf(w1, v1.x, acc1.x); acc1.y = fmaf(w1, v1.y, acc1.y);
        acc1.z = fmaf(w1, v1.z, acc1.z); acc1.w = fmaf(w1, v1.w, acc1.w);
        acc0.x = fmaf(w2, v2.x, acc0.x); acc0.y = fmaf(w2, v2.y, acc0.y);
        acc0.z = fmaf(w2, v2.z, acc0.z); acc0.w = fmaf(w2, v2.w, acc0.w);
        acc1.x = fmaf(w3, v3.x, acc1.x); acc1.y = fmaf(w3, v3.y, acc1.y);
        acc1.z = fmaf(w3, v3.z, acc1.z); acc1.w = fmaf(w3, v3.w, acc1.w);
    }
    for (; i < e; i++) {
        int2 p = __ldg(epack + i);
        float4 v = make_float4(0,0,0,0);
        if (act) v = __ldg(((const float4*)(src + (long)p.x * 96)) + lane);
        float cw = __int_as_float(p.y);
        acc0.x = fmaf(cw, v.x, acc0.x); acc0.y = fmaf(cw, v.y, acc0.y);
        acc0.z = fmaf(cw, v.z, acc0.z); acc0.w = fmaf(cw, v.w, acc0.w);
    }
    acc0.x += acc1.x; acc0.y += acc1.y; acc0.z += acc1.z; acc0.w += acc1.w;

    if (act) {
        ((float4*)(dst + (long)w * 96))[lane] = acc0;
        int c = lane * 4;
        atomicAdd(&ss[c+0], acc0.x);
        atomicAdd(&ss[c+1], acc0.y);
        atomicAdd(&ss[c+2], acc0.z);
        atomicAdd(&ss[c+3], acc0.w);
        atomicAdd(&ss[CH+c+0], acc0.x*acc0.x);
        atomicAdd(&ss[CH+c+1], acc0.y*acc0.y);
        atomicAdd(&ss[CH+c+2], acc0.z*acc0.z);
        atomicAdd(&ss[CH+c+3], acc0.w*acc0.w);
    }
    __syncthreads();
    if (tid < 2 * CH) atomicAdd(&stats[tid], ss[tid]);
}

// ============================================================================
// CSR gather (64 ch): half-warps own alternating edges, unroll-2 per half.
// Fused +bias + log_softmax.
// ============================================================================
__global__ void gather64_lsm_kernel(const int* __restrict__ starts,
                                    const int2* __restrict__ epack,
                                    const float* __restrict__ src,
                                    const float* __restrict__ b,
                                    float* __restrict__ out, int N) {
    int w = (blockIdx.x * blockDim.x + threadIdx.x) >> 5;
    int lane = threadIdx.x & 31;
    if (w >= N) return;
    int half = lane >> 4;
    int q = lane & 15;
    int s = __ldg(starts + w), e = __ldg(starts + w + 1);
    float4 acc0 = make_float4(0.f,0.f,0.f,0.f);
    float4 acc1 = make_float4(0.f,0.f,0.f,0.f);
    int i = s + half;
    for (; i + 2 < e; i += 4) {
        int2 p0 = __ldg(epack + i);
        int2 p1 = __ldg(epack + i + 2);
        float4 v0 = __ldg(((const float4*)(src + (long)p0.x * 64)) + q);
        float4 v1 = __ldg(((const float4*)(src + (long)p1.x * 64)) + q);
        float w0 = __int_as_float(p0.y), w1 = __int_as_float(p1.y);
        acc0.x = fmaf(w0, v0.x, acc0.x); acc0.y = fmaf(w0, v0.y, acc0.y);
        acc0.z = fmaf(w0, v0.z, acc0.z); acc0.w = fmaf(w0, v0.w, acc0.w);
        acc1.x = fmaf(w1, v1.x, acc1.x); acc1.y = fmaf(w1, v1.y, acc1.y);
        acc1.z = fmaf(w1, v1.z, acc1.z); acc1.w = fmaf(w1, v1.w, acc1.w);
    }
    for (; i < e; i += 2) {
        int2 p = __ldg(epack + i);
        float4 v = __ldg(((const float4*)(src + (long)p.x * 64)) + q);
        float cw = __int_as_float(p.y);
        acc0.x = fmaf(cw, v.x, acc0.x); acc0.y = fmaf(cw, v.y, acc0.y);
        acc0.z = fmaf(cw, v.z, acc0.z); acc0.w = fmaf(cw, v.w, acc0.w);
    }
    acc0.x += acc1.x; acc0.y += acc1.y; acc0.z += acc1.z; acc0.w += acc1.w;
    acc0.x += __shfl_xor_sync(0xFFFFFFFFu, acc0.x, 16);
    acc0.y += __shfl_xor_sync(0xFFFFFFFFu, acc0.y, 16);
    acc0.z += __shfl_xor_sync(0xFFFFFFFFu, acc0.z, 16);
    acc0.w += __shfl_xor_sync(0xFFFFFFFFu, acc0.w, 16);
    float4 bb = __ldg(((const float4*)b) + q);
    float v0 = acc0.x + bb.x, v1 = acc0.y + bb.y, v2 = acc0.z + bb.z, v3 = acc0.w + bb.w;
    float m = fmaxf(fmaxf(v0, v1), fmaxf(v2, v3));
#pragma unroll
    for (int o = 8; o; o >>= 1) m = fmaxf(m, __shfl_xor_sync(0xFFFFFFFFu, m, o));
    float sm = __expf(v0 - m) + __expf(v1 - m) + __expf(v2 - m) + __expf(v3 - m);
#pragma unroll
    for (int o = 8; o; o >>= 1) sm += __shfl_xor_sync(0xFFFFFFFFu, sm, o);
    float l = m + __logf(sm);
    if (half == 0)
        ((float4*)(out + (long)w * 64))[q] = make_float4(v0 - l, v1 - l, v2 - l, v3 - l);
}

// ============================================================================
extern "C" void kernel_launch(void* const* d_in, const int* in_sizes, int n_in,
                              void* d_out, int out_size) {
    const float* x   = (const float*)d_in[0];
    const float* ew  = (const float*)d_in[1];
    const int*   row = (const int*)  d_in[2];
    const int*   col = (const int*)  d_in[3];
    const float* W1  = (const float*)d_in[4];
    // b1 = d_in[5]  -- absorbed exactly by BatchNorm mean, skipped
    const float* W2  = (const float*)d_in[6];
    // b2 = d_in[7]  -- absorbed exactly by BatchNorm mean, skipped
    const float* W3  = (const float*)d_in[8];
    const float* b3  = (const float*)d_in[9];
    const float* g1  = (const float*)d_in[10];
    const float* be1 = (const float*)d_in[11];
    const float* g2  = (const float*)d_in[12];
    const float* be2 = (const float*)d_in[13];

    int N = in_sizes[0] / 128;
    int E = in_sizes[1];
    if (N > MAX_N) N = MAX_N;
    if (E > MAX_E) E = MAX_E;
    float* out = (float*)d_out;

    float *t, *agg, *stats;
    int *deg, *starts, *cursor;
    int2 *epack;
    cudaGetSymbolAddress((void**)&t,      d_t);
    cudaGetSymbolAddress((void**)&agg,    d_agg);
    cudaGetSymbolAddress((void**)&stats,  d_stats);
    cudaGetSymbolAddress((void**)&deg,    d_deg);
    cudaGetSymbolAddress((void**)&starts, d_starts);
    cudaGetSymbolAddress((void**)&cursor, d_cursor);
    cudaGetSymbolAddress((void**)&epack,  d_epack);

    float* stats1 = stats;            // layer-1 output stats
    float* stats2 = stats + 2 * CH;   // layer-2 output stats

    int gblocks = (N + 31) / 32;
    int eblocks = (E + 255) / 256;
    int nwarp_blocks = (N * 32 + 255) / 256;

    // ---------------- CSR build (also zeros both stats buffers) -------------
    cudaMemsetAsync(deg, 0, (long)N * sizeof(int));
    hist_kernel<<<eblocks, 256>>>(row, deg, E);
    scan_kernel<<<1, 1024>>>(deg, starts, cursor, stats, N);
    permute_kernel<<<eblocks, 256>>>(row, col, ew, cursor, epack, E);

    // ---------------- Layer 1: x[N,128] @ W1 -> gather(+stats1) -> agg ------
    gemm_bn_kernel<128,96><<<gblocks, dim3(24,8)>>>(x, W1, nullptr, nullptr, nullptr, t, N);
    gather96_stats_kernel<<<nwarp_blocks, 256>>>(starts, epack, t, agg, stats1, N);

    // ---------------- Layer 2: relu(bn(agg)) @ W2 -> gather(+stats2) --------
    gemm_bn_kernel<96,96><<<gblocks, dim3(24,8)>>>(agg, W2, stats1, g1, be1, t, N);
    gather96_stats_kernel<<<nwarp_blocks, 256>>>(starts, epack, t, agg, stats2, N);

    // ---------------- Layer 3: relu(bn(agg)) @ W3 -> gather+lsm -> out ------
    gemm_bn_kernel<96,64><<<gblocks, dim3(16,8)>>>(agg, W3, stats2, g2, be2, t, N);
    gather64_lsm_kernel<<<nwarp_blocks, 256>>>(starts, epack, t, b3, out, N);
}

// round 7
// speedup vs baseline: 1.0777x; 1.0523x over previous
#include <cuda_runtime.h>
#include <cuda_bf16.h>
#include <math.h>

#define MAX_N 50000
#define MAX_E 800000
#define CH    96
#define BN_EPS 1e-5f

// -------- scratch (device globals; no allocation allowed) --------
__device__ float d_t   [MAX_N * CH];     // GEMM output (pre-aggregation)
__device__ float d_agg [MAX_N * CH];     // aggregation output
__device__ float d_stats[4 * CH];        // [sum1|sq1|sum2|sq2]
// CSR build scratch
__device__ int   d_deg   [MAX_N];
__device__ int   d_starts[MAX_N + 1];
__device__ int   d_cursor[MAX_N];
__device__ int2  d_epack [MAX_E];        // packed (col, bitcast(ew))

// -------- packed f32x2 helpers (Blackwell FFMA2 path) --------
__device__ __forceinline__ unsigned long long ffma2(unsigned long long a,
                                                    unsigned long long b,
                                                    unsigned long long c) {
    unsigned long long d;
    asm("fma.rn.f32x2 %0, %1, %2, %3;" : "=l"(d) : "l"(a), "l"(b), "l"(c));
    return d;
}
__device__ __forceinline__ unsigned long long bcast2(float x) {
    unsigned long long d;
    asm("mov.b64 %0, {%1, %1};" : "=l"(d) : "f"(x));
    return d;
}
__device__ __forceinline__ float2 unpack2(unsigned long long p) {
    float lo, hi;
    asm("mov.b64 {%0, %1}, %2;" : "=f"(lo), "=f"(hi) : "l"(p));
    return make_float2(lo, hi);
}

// ============================================================================
// CSR build: histogram -> scan (also zeros stats) -> permute
// ============================================================================
__global__ void hist_kernel(const int* __restrict__ row, int* __restrict__ deg, int E) {
    int i = blockIdx.x * blockDim.x + threadIdx.x;
    if (i < E) atomicAdd(&deg[row[i]], 1);
}

__global__ void scan_kernel(const int* __restrict__ deg,
                            int* __restrict__ starts,
                            int* __restrict__ cursor,
                            float* __restrict__ stats, int N) {
    __shared__ int part[1024];
    int t = threadIdx.x;
    if (t < 4 * CH) stats[t] = 0.f;
    int chunk = (N + 1023) / 1024;
    int lo = t * chunk;
    int hi = lo + chunk; if (hi > N) hi = N; if (lo > N) lo = N;
    int s = 0;
    for (int i = lo; i < hi; i++) s += deg[i];
    part[t] = s;
    __syncthreads();
    for (int o = 1; o < 1024; o <<= 1) {
        int v = (t >= o) ? part[t - o] : 0;
        __syncthreads();
        part[t] += v;
        __syncthreads();
    }
    int base = (t == 0) ? 0 : part[t - 1];
    for (int i = lo; i < hi; i++) {
        starts[i] = base;
        cursor[i] = base;
        base += deg[i];
    }
    if (t == 1023) starts[N] = part[1023];
}

__global__ void permute_kernel(const int* __restrict__ row,
                               const int* __restrict__ col,
                               const float* __restrict__ ew,
                               int* __restrict__ cursor,
                               int2* __restrict__ epack, int E) {
    int i = blockIdx.x * blockDim.x + threadIdx.x;
    if (i >= E) return;
    int p = atomicAdd(&cursor[row[i]], 1);
    epack[p] = make_int2(col[i], __float_as_int(ew[i]));
}

// ============================================================================
// Register-blocked GEMM, K-chunked (KC=32), 32 rows/block, 4x4 per thread,
// FFMA2 inner loop (packed f32x2, row-paired accumulators).
// Optional fused BatchNorm+ReLU on the INPUT (scale/shift from raw stats).
// ============================================================================
template<int CIN, int COUT>
__global__ void gemm_bn_kernel(const float* __restrict__ A,
                               const float* __restrict__ W,
                               const float* __restrict__ stats,
                               const float* __restrict__ gamma,
                               const float* __restrict__ beta,
                               float* __restrict__ C, int nrows) {
    constexpr int TM = 32;
    constexpr int KC = 32;
    constexpr int TX = COUT / 4;
    constexpr int TY = TM / 4;
    constexpr int NT = TX * TY;
    constexpr int APAD = TM + 4;
    constexpr int KGC = KC / 4;

    __shared__ float Ws[KC * COUT];
    __shared__ float As[KC * APAD];
    __shared__ float Sc[CIN];
    __shared__ float Sh[CIN];

    int tid = threadIdx.y * TX + threadIdx.x;
    int row0 = blockIdx.x * TM;
    int c0 = threadIdx.x * 4;
    int r0 = threadIdx.y * 4;

    bool has_bn = (gamma != nullptr);
    if (has_bn) {
        float n = (float)nrows;
        for (int i = tid; i < CIN; i += NT) {
            float mean = stats[i] / n;
            float var  = stats[CIN + i] / n - mean * mean;
            float inv  = rsqrtf(var + BN_EPS);
            float sc   = gamma[i] * inv;
            Sc[i] = sc;
            Sh[i] = beta[i] - mean * sc;
        }
        __syncthreads();
    }

    // accp[rp][c]: packed pair (row r0+2rp, row r0+2rp+1) for column c0+c
    unsigned long long accp[2][4];
#pragma unroll
    for (int rp = 0; rp < 2; rp++)
#pragma unroll
        for (int c = 0; c < 4; c++) accp[rp][c] = 0ULL;

    for (int k0 = 0; k0 < CIN; k0 += KC) {
        for (int i = tid; i < KC * COUT / 4; i += NT)
            ((float4*)Ws)[i] = ((const float4*)(W + k0 * COUT))[i];
        for (int i = tid; i < TM * KGC; i += NT) {
            int r  = i / KGC;
            int kg = i % KGC;
            int grow = row0 + r;
            float4 v = make_float4(0.f, 0.f, 0.f, 0.f);
            if (grow < nrows)
                v = *(const float4*)(A + (long)grow * CIN + k0 + kg * 4);
            if (has_bn) {
                int k = k0 + kg * 4;
                v.x = fmaxf(fmaf(v.x, Sc[k+0], Sh[k+0]), 0.f);
                v.y = fmaxf(fmaf(v.y, Sc[k+1], Sh[k+1]), 0.f);
                v.z = fmaxf(fmaf(v.z, Sc[k+2], Sh[k+2]), 0.f);
                v.w = fmaxf(fmaf(v.w, Sc[k+3], Sh[k+3]), 0.f);
            }
            As[(kg*4+0) * APAD + r] = v.x;
            As[(kg*4+1) * APAD + r] = v.y;
            As[(kg*4+2) * APAD + r] = v.z;
            As[(kg*4+3) * APAD + r] = v.w;
        }
        __syncthreads();

#pragma unroll 8
        for (int kk = 0; kk < KC; kk++) {
            float4 w = *(const float4*)(Ws + kk * COUT + c0);
            // row pairs (a0,a1),(a2,a3) come out of LDS.128 pre-packed
            ulonglong2 av = *(const ulonglong2*)(As + kk * APAD + r0);
            unsigned long long wx = bcast2(w.x), wy = bcast2(w.y);
            unsigned long long wz = bcast2(w.z), ww = bcast2(w.w);
            accp[0][0] = ffma2(av.x, wx, accp[0][0]);
            accp[0][1] = ffma2(av.x, wy, accp[0][1]);
            accp[0][2] = ffma2(av.x, wz, accp[0][2]);
            accp[0][3] = ffma2(av.x, ww, accp[0][3]);
            accp[1][0] = ffma2(av.y, wx, accp[1][0]);
            accp[1][1] = ffma2(av.y, wy, accp[1][1]);
            accp[1][2] = ffma2(av.y, wz, accp[1][2]);
            accp[1][3] = ffma2(av.y, ww, accp[1][3]);
        }
        __syncthreads();
    }

#pragma unroll
    for (int rp = 0; rp < 2; rp++) {
        float2 u0 = unpack2(accp[rp][0]);
        float2 u1 = unpack2(accp[rp][1]);
        float2 u2 = unpack2(accp[rp][2]);
        float2 u3 = unpack2(accp[rp][3]);
        int grow = row0 + r0 + rp * 2;
        if (grow < nrows)
            *(float4*)(C + (long)grow * COUT + c0) = make_float4(u0.x, u1.x, u2.x, u3.x);
        if (grow + 1 < nrows)
            *(float4*)(C + (long)(grow + 1) * COUT + c0) = make_float4(u0.y, u1.y, u2.y, u3.y);
    }
}

// ============================================================================
// CSR gather (96 ch, no atomics): one warp per node, lanes 0-23 own float4
// channel groups. Unrolled by 4 edges for MLP.
// ============================================================================
__global__ void gather96_kernel(const int* __restrict__ starts,
                                const int2* __restrict__ epack,
                                const float* __restrict__ src,
                                float* __restrict__ dst, int N) {
    int w = (blockIdx.x * blockDim.x + threadIdx.x) >> 5;
    int lane = threadIdx.x & 31;
    if (w >= N) return;
    int s = __ldg(starts + w), e = __ldg(starts + w + 1);
    bool act = lane < 24;
    float4 acc0 = make_float4(0.f,0.f,0.f,0.f);
    float4 acc1 = make_float4(0.f,0.f,0.f,0.f);
    int i = s;
    for (; i + 3 < e; i += 4) {
        int2 p0 = __ldg(epack + i);
        int2 p1 = __ldg(epack + i + 1);
        int2 p2 = __ldg(epack + i + 2);
        int2 p3 = __ldg(epack + i + 3);
        float4 v0 = make_float4(0,0,0,0), v1 = v0, v2 = v0, v3 = v0;
        if (act) {
            v0 = __ldg(((const float4*)(src + (long)p0.x * 96)) + lane);
            v1 = __ldg(((const float4*)(src + (long)p1.x * 96)) + lane);
            v2 = __ldg(((const float4*)(src + (long)p2.x * 96)) + lane);
            v3 = __ldg(((const float4*)(src + (long)p3.x * 96)) + lane);
        }
        float w0 = __int_as_float(p0.y), w1 = __int_as_float(p1.y);
        float w2 = __int_as_float(p2.y), w3 = __int_as_float(p3.y);
        acc0.x = fmaf(w0, v0.x, acc0.x); acc0.y = fmaf(w0, v0.y, acc0.y);
        acc0.z = fmaf(w0, v0.z, acc0.z); acc0.w = fmaf(w0, v0.w, acc0.w);
        acc1.x = fmaf(w1, v1.x, acc1.x); acc1.y = fmaf(w1, v1.y, acc1.y);
        acc1.z = fmaf(w1, v1.z, acc1.z); acc1.w = fmaf(w1, v1.w, acc1.w);
        acc0.x = fmaf(w2, v2.x, acc0.x); acc0.y = fmaf(w2, v2.y, acc0.y);
        acc0.z = fmaf(w2, v2.z, acc0.z); acc0.w = fmaf(w2, v2.w, acc0.w);
        acc1.x = fmaf(w3, v3.x, acc1.x); acc1.y = fmaf(w3, v3.y, acc1.y);
        acc1.z = fmaf(w3, v3.z, acc1.z); acc1.w = fmaf(w3, v3.w, acc1.w);
    }
    for (; i < e; i++) {
        int2 p = __ldg(epack + i);
        float4 v = make_float4(0,0,0,0);
        if (act) v = __ldg(((const float4*)(src + (long)p.x * 96)) + lane);
        float cw = __int_as_float(p.y);
        acc0.x = fmaf(cw, v.x, acc0.x); acc0.y = fmaf(cw, v.y, acc0.y);
        acc0.z = fmaf(cw, v.z, acc0.z); acc0.w = fmaf(cw, v.w, acc0.w);
    }
    acc0.x += acc1.x; acc0.y += acc1.y; acc0.z += acc1.z; acc0.w += acc1.w;
    if (act) ((float4*)(dst + (long)w * 96))[lane] = acc0;
}

// ============================================================================
// CSR gather (64 ch): half-warps own alternating edges, unroll-2 per half.
// Fused +bias + log_softmax.
// ============================================================================
__global__ void gather64_lsm_kernel(const int* __restrict__ starts,
                                    const int2* __restrict__ epack,
                                    const float* __restrict__ src,
                                    const float* __restrict__ b,
                                    float* __restrict__ out, int N) {
    int w = (blockIdx.x * blockDim.x + threadIdx.x) >> 5;
    int lane = threadIdx.x & 31;
    if (w >= N) return;
    int half = lane >> 4;
    int q = lane & 15;
    int s = __ldg(starts + w), e = __ldg(starts + w + 1);
    float4 acc0 = make_float4(0.f,0.f,0.f,0.f);
    float4 acc1 = make_float4(0.f,0.f,0.f,0.f);
    int i = s + half;
    for (; i + 2 < e; i += 4) {
        int2 p0 = __ldg(epack + i);
        int2 p1 = __ldg(epack + i + 2);
        float4 v0 = __ldg(((const float4*)(src + (long)p0.x * 64)) + q);
        float4 v1 = __ldg(((const float4*)(src + (long)p1.x * 64)) + q);
        float w0 = __int_as_float(p0.y), w1 = __int_as_float(p1.y);
        acc0.x = fmaf(w0, v0.x, acc0.x); acc0.y = fmaf(w0, v0.y, acc0.y);
        acc0.z = fmaf(w0, v0.z, acc0.z); acc0.w = fmaf(w0, v0.w, acc0.w);
        acc1.x = fmaf(w1, v1.x, acc1.x); acc1.y = fmaf(w1, v1.y, acc1.y);
        acc1.z = fmaf(w1, v1.z, acc1.z); acc1.w = fmaf(w1, v1.w, acc1.w);
    }
    for (; i < e; i += 2) {
        int2 p = __ldg(epack + i);
        float4 v = __ldg(((const float4*)(src + (long)p.x * 64)) + q);
        float cw = __int_as_float(p.y);
        acc0.x = fmaf(cw, v.x, acc0.x); acc0.y = fmaf(cw, v.y, acc0.y);
        acc0.z = fmaf(cw, v.z, acc0.z); acc0.w = fmaf(cw, v.w, acc0.w);
    }
    acc0.x += acc1.x; acc0.y += acc1.y; acc0.z += acc1.z; acc0.w += acc1.w;
    acc0.x += __shfl_xor_sync(0xFFFFFFFFu, acc0.x, 16);
    acc0.y += __shfl_xor_sync(0xFFFFFFFFu, acc0.y, 16);
    acc0.z += __shfl_xor_sync(0xFFFFFFFFu, acc0.z, 16);
    acc0.w += __shfl_xor_sync(0xFFFFFFFFu, acc0.w, 16);
    float4 bb = __ldg(((const float4*)b) + q);
    float v0 = acc0.x + bb.x, v1 = acc0.y + bb.y, v2 = acc0.z + bb.z, v3 = acc0.w + bb.w;
    float m = fmaxf(fmaxf(v0, v1), fmaxf(v2, v3));
#pragma unroll
    for (int o = 8; o; o >>= 1) m = fmaxf(m, __shfl_xor_sync(0xFFFFFFFFu, m, o));
    float sm = __expf(v0 - m) + __expf(v1 - m) + __expf(v2 - m) + __expf(v3 - m);
#pragma unroll
    for (int o = 8; o; o >>= 1) sm += __shfl_xor_sync(0xFFFFFFFFu, sm, o);
    float l = m + __logf(sm);
    if (half == 0)
        ((float4*)(out + (long)w * 64))[q] = make_float4(v0 - l, v1 - l, v2 - l, v3 - l);
}

// -------- BN stats: register-accumulating, one thread per channel ----------
__global__ void stats96_kernel(const float* __restrict__ h,
                               float* __restrict__ stats, int nrows) {
    int c = threadIdx.x;   // blockDim.x == 96
    float s = 0.f, q = 0.f;
    for (int r = blockIdx.x; r < nrows; r += gridDim.x) {
        float v = h[(long)r * 96 + c];
        s += v;
        q = fmaf(v, v, q);
    }
    atomicAdd(&stats[c], s);
    atomicAdd(&stats[96 + c], q);
}

// ============================================================================
extern "C" void kernel_launch(void* const* d_in, const int* in_sizes, int n_in,
                              void* d_out, int out_size) {
    const float* x   = (const float*)d_in[0];
    const float* ew  = (const float*)d_in[1];
    const int*   row = (const int*)  d_in[2];
    const int*   col = (const int*)  d_in[3];
    const float* W1  = (const float*)d_in[4];
    // b1 = d_in[5]  -- absorbed exactly by BatchNorm mean, skipped
    const float* W2  = (const float*)d_in[6];
    // b2 = d_in[7]  -- absorbed exactly by BatchNorm mean, skipped
    const float* W3  = (const float*)d_in[8];
    const float* b3  = (const float*)d_in[9];
    const float* g1  = (const float*)d_in[10];
    const float* be1 = (const float*)d_in[11];
    const float* g2  = (const float*)d_in[12];
    const float* be2 = (const float*)d_in[13];

    int N = in_sizes[0] / 128;
    int E = in_sizes[1];
    if (N > MAX_N) N = MAX_N;
    if (E > MAX_E) E = MAX_E;
    float* out = (float*)d_out;

    float *t, *agg, *stats;
    int *deg, *starts, *cursor;
    int2 *epack;
    cudaGetSymbolAddress((void**)&t,      d_t);
    cudaGetSymbolAddress((void**)&agg,    d_agg);
    cudaGetSymbolAddress((void**)&stats,  d_stats);
    cudaGetSymbolAddress((void**)&deg,    d_deg);
    cudaGetSymbolAddress((void**)&starts, d_starts);
    cudaGetSymbolAddress((void**)&cursor, d_cursor);
    cudaGetSymbolAddress((void**)&epack,  d_epack);

    float* stats1 = stats;            // layer-1 output stats
    float* stats2 = stats + 2 * CH;   // layer-2 output stats

    int gblocks = (N + 31) / 32;
    int eblocks = (E + 255) / 256;
    int nwarp_blocks = (N * 32 + 255) / 256;

    // ---------------- CSR build (also zeros both stats buffers) -------------
    cudaMemsetAsync(deg, 0, (long)N * sizeof(int));
    hist_kernel<<<eblocks, 256>>>(row, deg, E);
    scan_kernel<<<1, 1024>>>(deg, starts, cursor, stats, N);
    permute_kernel<<<eblocks, 256>>>(row, col, ew, cursor, epack, E);

    // ---------------- Layer 1: x[N,128] @ W1 -> gather -> agg ---------------
    gemm_bn_kernel<128,96><<<gblocks, dim3(24,8)>>>(x, W1, nullptr, nullptr, nullptr, t, N);
    gather96_kernel<<<nwarp_blocks, 256>>>(starts, epack, t, agg, N);
    stats96_kernel<<<1024, 96>>>(agg, stats1, N);

    // ---------------- Layer 2: relu(bn(agg)) @ W2 -> gather -> agg ----------
    gemm_bn_kernel<96,96><<<gblocks, dim3(24,8)>>>(agg, W2, stats1, g1, be1, t, N);
    gather96_kernel<<<nwarp_blocks, 256>>>(starts, epack, t, agg, N);
    stats96_kernel<<<1024, 96>>>(agg, stats2, N);

    // ---------------- Layer 3: relu(bn(agg)) @ W3 -> gather+lsm -> out ------
    gemm_bn_kernel<96,64><<<gblocks, dim3(16,8)>>>(agg, W3, stats2, g2, be2, t, N);
    gather64_lsm_kernel<<<nwarp_blocks, 256>>>(starts, epack, t, b3, out, N);
}